// round 1
// baseline (speedup 1.0000x reference)
#include <cuda_runtime.h>
#include <math_constants.h>

// Morphological opening: 10x10 erosion (min, +inf pad) then 10x10 dilation
// (max, -inf pad), SAME padding (pad_lo=4, pad_hi=5), on NHWC [16,512,512,8] f32.
// Fully fused: one block computes a 32x32 spatial tile x all 8 channels.
// Input halo: erosion needs rows/cols [i-4, i+5]; dilation output needs eroded
// [j-4, j+5] -> input [j-8, j+10] => 18 extra rows/cols per tile.

#define B_   16
#define H_   512
#define W_   512
#define C_   8
#define TH   32
#define TW   32
#define IN_R   (TH + 18)        // 50 input rows
#define IN_C   (TW + 18)        // 50 input cols
#define IN_CF  (IN_C * C_)      // 400 fused (col,channel)
#define ER_C   (TW + 9)         // 41 eroded cols (with +-(4,5) halo for dilation)
#define ER_R   (TH + 9)         // 41 eroded rows
#define ER_CF  (ER_C * C_)      // 328
#define OUT_CF (TW * C_)        // 256
#define NT   512

#define SMEM_A_FLOATS (IN_R * IN_CF)   // 20000
#define SMEM_B_FLOATS (IN_R * ER_CF)   // 16400
#define SMEM_BYTES ((SMEM_A_FLOATS + SMEM_B_FLOATS) * 4)  // 145600

__global__ __launch_bounds__(NT, 1)
void opening_kernel(const float* __restrict__ in, float* __restrict__ out) {
    extern __shared__ float smem[];
    float* A  = smem;                    // input tile, later eroded tile
    float* Bf = smem + SMEM_A_FLOATS;    // row-min, later row-max

    const int b   = blockIdx.z;
    const int gh0 = blockIdx.y * TH;
    const int gw0 = blockIdx.x * TW;
    const int tid = threadIdx.x;

    const float* inb = in + (size_t)b * H_ * W_ * C_;

    // ---- Load input tile with +inf padding outside the image ----
    // Global row gr = gh0 + r - 8, global col gc = gw0 + cc - 8.
    #pragma unroll 1
    for (int i = tid; i < IN_R * IN_CF; i += NT) {
        int r  = i / IN_CF;
        int cF = i - r * IN_CF;
        int cc = cF >> 3;
        int gr = gh0 + r - 8;
        int gc = gw0 + cc - 8;
        float v = CUDART_INF_F;
        if (gr >= 0 && gr < H_ && gc >= 0 && gc < W_)
            v = inb[((size_t)gr * W_ + gw0 - 8) * C_ + cF];
        A[i] = v;
    }
    __syncthreads();

    // ---- Stage 1: row-wise min (along W). B[r][cF2] over 10 taps stride 8 ----
    #pragma unroll 1
    for (int i = tid; i < IN_R * ER_CF; i += NT) {
        int r  = i / ER_CF;
        int cF = i - r * ER_CF;
        const float* p = A + r * IN_CF + cF;
        float v = p[0];
        #pragma unroll
        for (int k = 1; k < 10; k++) v = fminf(v, p[k * 8]);
        Bf[i] = v;
    }
    __syncthreads();

    // ---- Stage 2: col-wise min -> eroded, then force -inf outside image ----
    // Eroded global row = gh0 + e - 4, eroded global col = gw0 + (cF>>3) - 4.
    #pragma unroll 1
    for (int i = tid; i < ER_R * ER_CF; i += NT) {
        int e  = i / ER_CF;
        int cF = i - e * ER_CF;
        const float* p = Bf + i;
        float v = p[0];
        #pragma unroll
        for (int k = 1; k < 10; k++) v = fminf(v, p[k * ER_CF]);
        int ger = gh0 + e - 4;
        int gec = gw0 + (cF >> 3) - 4;
        if (ger < 0 || ger >= H_ || gec < 0 || gec >= W_) v = -CUDART_INF_F;
        A[i] = v;   // A input data no longer needed
    }
    __syncthreads();

    // ---- Stage 3: row-wise max over eroded ----
    #pragma unroll 1
    for (int i = tid; i < ER_R * OUT_CF; i += NT) {
        int e  = i / OUT_CF;
        int cF = i - e * OUT_CF;
        const float* p = A + e * ER_CF + cF;
        float v = p[0];
        #pragma unroll
        for (int k = 1; k < 10; k++) v = fmaxf(v, p[k * 8]);
        Bf[i] = v;  // Bf row-min data no longer needed
    }
    __syncthreads();

    // ---- Stage 4: col-wise max + store (WEIGHT = 1.0) ----
    float* outb = out + (size_t)b * H_ * W_ * C_;
    #pragma unroll 1
    for (int i = tid; i < TH * OUT_CF; i += NT) {
        int r  = i / OUT_CF;
        int cF = i - r * OUT_CF;
        const float* p = Bf + i;
        float v = p[0];
        #pragma unroll
        for (int k = 1; k < 10; k++) v = fmaxf(v, p[k * OUT_CF]);
        outb[((size_t)(gh0 + r) * W_ + gw0) * C_ + cF] = v * 1.0f;
    }
}

extern "C" void kernel_launch(void* const* d_in, const int* in_sizes, int n_in,
                              void* d_out, int out_size) {
    const float* in = (const float*)d_in[0];
    float* out = (float*)d_out;

    cudaFuncSetAttribute(opening_kernel,
                         cudaFuncAttributeMaxDynamicSharedMemorySize, SMEM_BYTES);

    dim3 grid(W_ / TW, H_ / TH, B_);
    opening_kernel<<<grid, NT, SMEM_BYTES>>>(in, out);
}

// round 2
// speedup vs baseline: 2.2176x; 2.2176x over previous
#include <cuda_runtime.h>
#include <math_constants.h>

// Morphological opening (10x10 min then 10x10 max, SAME pad lo=4/hi=5),
// NHWC [16,512,512,8] f32. Fused single kernel.
// Each block: 32x32 spatial tile x 4 channels (one float4). grid.z = batch*2.
// Smem 71.1KB/block -> 3 blocks/SM (vs 1 before): occupancy 25% -> 75%.

#define B_   16
#define H_   512
#define W_   512
#define TH   32
#define TW   32
#define IN_R   (TH + 18)        // 50
#define IN_C   (TW + 18)        // 50
#define ER_C   (TW + 9)         // 41
#define ER_R   (TH + 9)         // 41
#define NT   512

#define A_ELEMS (IN_R * IN_C)   // 2500 float4
#define B_ELEMS (IN_R * ER_C)   // 2050 float4
#define SMEM_BYTES ((A_ELEMS + B_ELEMS) * 16)   // 72800 B

__device__ __forceinline__ float4 min4(float4 a, float4 b) {
    return make_float4(fminf(a.x,b.x), fminf(a.y,b.y), fminf(a.z,b.z), fminf(a.w,b.w));
}
__device__ __forceinline__ float4 max4(float4 a, float4 b) {
    return make_float4(fmaxf(a.x,b.x), fmaxf(a.y,b.y), fmaxf(a.z,b.z), fmaxf(a.w,b.w));
}

// 10-tap min over p[0], p[s], ..., p[9s], register-light pairwise tree.
__device__ __forceinline__ float4 min10(const float4* p, int s) {
    float4 a0 = p[0],   a1 = p[s],   a2 = p[2*s], a3 = p[3*s];
    float4 v  = min4(min4(a0, a1), min4(a2, a3));
    a0 = p[4*s]; a1 = p[5*s]; a2 = p[6*s]; a3 = p[7*s];
    v  = min4(v, min4(min4(a0, a1), min4(a2, a3)));
    a0 = p[8*s]; a1 = p[9*s];
    return min4(v, min4(a0, a1));
}
__device__ __forceinline__ float4 max10(const float4* p, int s) {
    float4 a0 = p[0],   a1 = p[s],   a2 = p[2*s], a3 = p[3*s];
    float4 v  = max4(max4(a0, a1), max4(a2, a3));
    a0 = p[4*s]; a1 = p[5*s]; a2 = p[6*s]; a3 = p[7*s];
    v  = max4(v, max4(max4(a0, a1), max4(a2, a3)));
    a0 = p[8*s]; a1 = p[9*s];
    return max4(v, max4(a0, a1));
}

__global__ __launch_bounds__(NT, 3)
void opening_kernel(const float4* __restrict__ in4, float4* __restrict__ out4) {
    extern __shared__ float4 smem[];
    float4* A  = smem;             // input tile, later eroded tile
    float4* Bf = smem + A_ELEMS;   // row-min, later row-max

    const int b   = blockIdx.z >> 1;
    const int g   = blockIdx.z & 1;          // channel half (float4 index)
    const int gh0 = blockIdx.y * TH;
    const int gw0 = blockIdx.x * TW;
    const int tid = threadIdx.x;

    const size_t base = (size_t)b * H_ * W_ * 2 + g;

    // ---- Load input tile (+inf outside image) ----
    const float4 INF4 = make_float4(CUDART_INF_F, CUDART_INF_F, CUDART_INF_F, CUDART_INF_F);
    for (int i = tid; i < A_ELEMS; i += NT) {
        int r  = i / IN_C;
        int c  = i - r * IN_C;
        int gr = gh0 + r - 8;
        int gc = gw0 + c - 8;
        float4 v = INF4;
        if (gr >= 0 && gr < H_ && gc >= 0 && gc < W_)
            v = in4[base + ((size_t)gr * W_ + gc) * 2];
        A[i] = v;
    }
    __syncthreads();

    // ---- Stage 1: horizontal min (window 10 along cols) ----
    for (int i = tid; i < IN_R * ER_C; i += NT) {
        int r = i / ER_C;
        int c = i - r * ER_C;
        Bf[i] = min10(A + r * IN_C + c, 1);
    }
    __syncthreads();

    // ---- Stage 2: vertical min -> eroded; force -inf outside image ----
    for (int i = tid; i < ER_R * ER_C; i += NT) {
        int e = i / ER_C;
        int c = i - e * ER_C;
        float4 v = min10(Bf + i, ER_C);
        int ger = gh0 + e - 4;
        int gec = gw0 + c - 4;
        if (ger < 0 || ger >= H_ || gec < 0 || gec >= W_)
            v = make_float4(-CUDART_INF_F, -CUDART_INF_F, -CUDART_INF_F, -CUDART_INF_F);
        A[i] = v;                       // input tile no longer needed
    }
    __syncthreads();

    // ---- Stage 3: horizontal max over eroded ----
    for (int i = tid; i < ER_R * TW; i += NT) {
        int e = i / TW;
        int c = i - e * TW;
        Bf[i] = max10(A + e * ER_C + c, 1);
    }
    __syncthreads();

    // ---- Stage 4: vertical max + store (WEIGHT = 1.0) ----
    for (int i = tid; i < TH * TW; i += NT) {
        int r = i / TW;
        int c = i - r * TW;
        float4 v = max10(Bf + i, TW);
        out4[base + ((size_t)(gh0 + r) * W_ + (gw0 + c)) * 2] = v;
    }
}

extern "C" void kernel_launch(void* const* d_in, const int* in_sizes, int n_in,
                              void* d_out, int out_size) {
    const float4* in  = (const float4*)d_in[0];
    float4* out = (float4*)d_out;

    cudaFuncSetAttribute(opening_kernel,
                         cudaFuncAttributeMaxDynamicSharedMemorySize, SMEM_BYTES);

    dim3 grid(W_ / TW, H_ / TH, B_ * 2);
    opening_kernel<<<grid, NT, SMEM_BYTES>>>(in, out);
}

// round 3
// speedup vs baseline: 3.9017x; 1.7594x over previous
#include <cuda_runtime.h>
#include <math_constants.h>

// Morphological opening (10x10 min, then 10x10 max; SAME pad lo=4/hi=5),
// NHWC [16,512,512,8] f32. Fused single kernel, van Herk / Gil-Werman
// sliding windows: ~1.9 smem loads + 2.8 min-ops per output instead of 10/10.
// Block = 32x32 spatial tile x 4 channels (float4). 73.6KB smem -> 3 blocks/SM.

#define B_   16
#define H_   512
#define W_   512
#define TH   32
#define TW   32
#define IN_R 50
#define IN_C 50
#define IN_CP 51          // padded row stride (conflict-free row-strided access)
#define ER_R 41
#define ER_C 41           // B-buffer row stride (naturally conflict-free)
#define NT   256

#define A_ELEMS (IN_R * IN_CP)   // 2550 float4
#define B_ELEMS (IN_R * ER_C)    // 2050 float4
#define SMEM_BYTES ((A_ELEMS + B_ELEMS) * 16)   // 73600 B

__device__ __forceinline__ float4 min4(float4 a, float4 b) {
    return make_float4(fminf(a.x,b.x), fminf(a.y,b.y), fminf(a.z,b.z), fminf(a.w,b.w));
}
__device__ __forceinline__ float4 max4(float4 a, float4 b) {
    return make_float4(fmaxf(a.x,b.x), fmaxf(a.y,b.y), fmaxf(a.z,b.z), fmaxf(a.w,b.w));
}

// van Herk segment: outputs out[j] = OP(in[j .. j+9]) for j in [0, count),
// where in = p[0], p[stepIn], ... ; count <= 10 and p[0..9] always readable.
template<bool MIN, typename OutPtr>
__device__ __forceinline__ void vanherk(const float4* __restrict__ p, int stepIn,
                                        OutPtr q, long stepOut, int count) {
    float4 x[10];
    #pragma unroll
    for (int j = 0; j < 10; j++) x[j] = p[j * stepIn];
    #pragma unroll
    for (int j = 8; j >= 0; j--) x[j] = MIN ? min4(x[j], x[j+1]) : max4(x[j], x[j+1]);
    float4 pr = x[9];
    q[0] = MIN ? min4(x[0], pr) : max4(x[0], pr);
    #pragma unroll
    for (int j = 1; j < 10; j++) {
        if (j >= count) break;
        float4 xn = p[(j + 9) * stepIn];
        pr = MIN ? min4(pr, xn) : max4(pr, xn);
        q[j * stepOut] = MIN ? min4(x[j], pr) : max4(x[j], pr);
    }
}

__global__ __launch_bounds__(NT, 3)
void opening_kernel(const float4* __restrict__ in4, float4* __restrict__ out4) {
    extern __shared__ float4 smem[];
    float4* A  = smem;             // input tile (51-stride), later eroded tile
    float4* Bf = smem + A_ELEMS;   // row-min (41-stride), later row-max

    const int b   = blockIdx.z >> 1;
    const int g   = blockIdx.z & 1;
    const int gh0 = blockIdx.y * TH;
    const int gw0 = blockIdx.x * TW;
    const int tid = threadIdx.x;

    const size_t base = (size_t)b * H_ * W_ * 2 + g;

    // ---- Load input tile (+inf outside image) ----
    const float4 INF4 = make_float4(CUDART_INF_F, CUDART_INF_F, CUDART_INF_F, CUDART_INF_F);
    for (int i = tid; i < IN_R * IN_C; i += NT) {
        int r  = i / IN_C;
        int c  = i - r * IN_C;
        int gr = gh0 + r - 8;
        int gc = gw0 + c - 8;
        float4 v = INF4;
        if (gr >= 0 && gr < H_ && gc >= 0 && gc < W_)
            v = in4[base + ((size_t)gr * W_ + gc) * 2];
        A[r * IN_CP + c] = v;
    }
    __syncthreads();

    // ---- Stage 1: horizontal min. 50 rows x 5 segments = 250 tasks ----
    if (tid < 250) {
        int r = tid % 50, s = tid / 50;
        int c0 = s * 10;
        int count = (s == 4) ? 1 : 10;          // 41 output cols
        vanherk<true>(A + r * IN_CP + c0, 1, Bf + r * ER_C + c0, 1L, count);
    }
    __syncthreads();

    // ---- Stage 2: vertical min -> eroded (+ -inf outside image). 41x5=205 ----
    if (tid < 205) {
        int c = tid % 41, s = tid / 41;
        int e0 = s * 10;
        int count = (s == 4) ? 1 : 10;          // 41 output rows
        const float4* p = Bf + e0 * ER_C + c;
        float4 x[10];
        #pragma unroll
        for (int j = 0; j < 10; j++) x[j] = p[j * ER_C];
        #pragma unroll
        for (int j = 8; j >= 0; j--) x[j] = min4(x[j], x[j+1]);
        float4 pr = x[9];
        int  gec   = gw0 + c - 4;
        bool colOK = (gec >= 0 && gec < W_);
        const float4 NINF4 = make_float4(-CUDART_INF_F, -CUDART_INF_F,
                                         -CUDART_INF_F, -CUDART_INF_F);
        float4* q = A + e0 * IN_CP + c;
        #pragma unroll
        for (int j = 0; j < 10; j++) {
            if (j >= count) break;
            if (j > 0) pr = min4(pr, p[(j + 9) * ER_C]);
            float4 v = min4(x[j], pr);
            int ger = gh0 + e0 + j - 4;
            if (!colOK || ger < 0 || ger >= H_) v = NINF4;
            q[j * IN_CP] = v;
        }
    }
    __syncthreads();

    // ---- Stage 3: horizontal max over eroded. 41 rows x 4 segments = 164 ----
    if (tid < 164) {
        int e = tid % 41, s = tid / 41;
        int c0 = s * 10;
        int count = (s == 3) ? 2 : 10;          // 32 output cols
        vanherk<false>(A + e * IN_CP + c0, 1, Bf + e * ER_C + c0, 1L, count);
    }
    __syncthreads();

    // ---- Stage 4: vertical max, store to gmem. 32 cols x 4 segments = 128 ----
    if (tid < 128) {
        int c = tid % 32, s = tid / 32;
        int r0 = s * 10;
        int count = (s == 3) ? 2 : 10;          // 32 output rows
        float4* q = out4 + base + ((size_t)(gh0 + r0) * W_ + gw0 + c) * 2;
        vanherk<false>(Bf + r0 * ER_C + c, ER_C, q, (long)W_ * 2, count);
    }
}

extern "C" void kernel_launch(void* const* d_in, const int* in_sizes, int n_in,
                              void* d_out, int out_size) {
    const float4* in  = (const float4*)d_in[0];
    float4* out = (float4*)d_out;

    cudaFuncSetAttribute(opening_kernel,
                         cudaFuncAttributeMaxDynamicSharedMemorySize, SMEM_BYTES);

    dim3 grid(W_ / TW, H_ / TH, B_ * 2);
    opening_kernel<<<grid, NT, SMEM_BYTES>>>(in, out);
}